// round 7
// baseline (speedup 1.0000x reference)
#include <cuda_runtime.h>
#include <cuda_fp16.h>
#include <cstdint>

#define BB 32768
#define II 256
#define HH 512
#define KK 768        // I + H, single fp16 pass
#define NN 2048       // 4 * H gates

__device__ __half g_A[(size_t)BB * KK];   // [B][K]  fp16
__device__ __half g_W[(size_t)NN * KK];   // [N][K]  fp16, N interleaved (u,g)
__device__ float g_bias[NN];

// ---------------------------------------------------------------------------
// PTX helpers
// ---------------------------------------------------------------------------
__device__ __forceinline__ void cp_async16(uint32_t saddr, const void* gaddr) {
    asm volatile("cp.async.cg.shared.global [%0], [%1], 16;\n"
                 :: "r"(saddr), "l"(gaddr));
}
__device__ __forceinline__ void ldsm_x4(uint32_t* r, uint32_t addr) {
    asm volatile("ldmatrix.sync.aligned.m8n8.x4.shared.b16 {%0,%1,%2,%3}, [%4];\n"
                 : "=r"(r[0]), "=r"(r[1]), "=r"(r[2]), "=r"(r[3]) : "r"(addr));
}
__device__ __forceinline__ void mma16816(float* d, const uint32_t* a, const uint32_t* b) {
    asm volatile(
        "mma.sync.aligned.m16n8k16.row.col.f32.f16.f16.f32 "
        "{%0,%1,%2,%3}, {%4,%5,%6,%7}, {%8,%9}, {%0,%1,%2,%3};\n"
        : "+f"(d[0]), "+f"(d[1]), "+f"(d[2]), "+f"(d[3])
        : "r"(a[0]), "r"(a[1]), "r"(a[2]), "r"(a[3]), "r"(b[0]), "r"(b[1]));
}

// ---------------------------------------------------------------------------
// Merged prep kernel (fp16 A, W, bias). Gate cols interleaved:
// out col n <-> (u=n>>2, g=n&3); src row = g*H+u.
// ---------------------------------------------------------------------------
#define NB_A (BB * (KK / 4) / 256)     // 24576
#define NB_W (NN * (KK / 4) / 256)     // 1536

__global__ void prep_all(const float* __restrict__ x, const float* __restrict__ h,
                         const float* __restrict__ Wx, const float* __restrict__ bx,
                         const float* __restrict__ Wh, const float* __restrict__ bh) {
    int bidx = blockIdx.x;
    if (bidx < NB_A) {
        int idx = bidx * 256 + threadIdx.x;
        int b = idx / (KK / 4), kc = idx % (KK / 4);
        int k0 = kc * 4;
        float4 v;
        if (k0 < II) v = *(const float4*)(x + (size_t)b * II + k0);
        else         v = *(const float4*)(h + (size_t)b * HH + (k0 - II));
        union { __half h[4]; uint2 u2; } p;
        p.h[0] = __float2half_rn(v.x); p.h[1] = __float2half_rn(v.y);
        p.h[2] = __float2half_rn(v.z); p.h[3] = __float2half_rn(v.w);
        *(uint2*)(g_A + (size_t)b * KK + k0) = p.u2;
    } else {
        int idx = (bidx - NB_A) * 256 + threadIdx.x;
        int n = idx / (KK / 4), kc = idx % (KK / 4);
        int u = n >> 2, g = n & 3, src = g * HH + u;
        int k0 = kc * 4;
        float4 v;
        if (k0 < II) v = *(const float4*)(Wx + (size_t)src * II + k0);
        else         v = *(const float4*)(Wh + (size_t)src * HH + (k0 - II));
        union { __half h[4]; uint2 u2; } p;
        p.h[0] = __float2half_rn(v.x); p.h[1] = __float2half_rn(v.y);
        p.h[2] = __float2half_rn(v.z); p.h[3] = __float2half_rn(v.w);
        *(uint2*)(g_W + (size_t)n * KK + k0) = p.u2;
        if (kc == 0) g_bias[n] = bx[src] + bh[src];
    }
}

// ---------------------------------------------------------------------------
// Fused GEMM + LSTM epilogue.
// CTA tile 128(M) x 256(N), K chunk 64, 3-stage cp.async ring, one sync/iter.
// 8 warps in 2(M) x 4(N) grid; warp tile 64x64 (4x8 m16n8 mma tiles).
// Rows 128B with XOR-8 swizzle (conflict-free ldmatrix). 1 CTA/SM, 144KB smem.
// ---------------------------------------------------------------------------
#define KCH 64
#define NK  (KK / KCH)        // 12
#define ROWB 128              // bytes per smem row (64 halves, swizzled)
#define ASTG (128 * ROWB)     // 16384 (A tile: 128 rows)
#define BSTG (256 * ROWB)     // 32768 (B tile: 256 rows)
#define STG  (ASTG + BSTG)    // 49152 per stage
#define NSTAGE 3
#define SMEM_DYN (NSTAGE * STG)   // 147456
#define EGS_STRIDE 264        // floats; 1056B = 16B-aligned rows

__global__ void __launch_bounds__(256, 1)
lstm_gemm(const float* __restrict__ c_in, float* __restrict__ out) {
    extern __shared__ __align__(16) unsigned char smem[];
    __shared__ float bias_s[256];

    const int tid  = threadIdx.x;
    const int warp = tid >> 5, lane = tid & 31;
    const int wm = warp & 1, wn = warp >> 1;       // 2(M) x 4(N) warp grid
    const int mBase = blockIdx.y * 128;
    const int nBase = blockIdx.x * 256;

    const uint32_t sbase = (uint32_t)__cvta_generic_to_shared(smem);
    bias_s[tid] = g_bias[nBase + tid];

    float acc[4][8][4];
#pragma unroll
    for (int mi = 0; mi < 4; mi++)
#pragma unroll
        for (int ni = 0; ni < 8; ni++)
#pragma unroll
            for (int d = 0; d < 4; d++) acc[mi][ni][d] = 0.f;

    const __half* gAp = g_A + (size_t)mBase * KK;
    const __half* gWp = g_W + (size_t)nBase * KK;

    // A: 128 rows x 8 chunks(16B) = 1024 -> 4/thread. B: 256 x 8 = 2048 -> 8/thread.
    auto load_stage = [&](int kt, int stage) {
        uint32_t so = sbase + stage * STG;
#pragma unroll
        for (int j = 0; j < 4; j++) {
            int idx = tid + j * 256;
            int row = idx >> 3, ch = idx & 7;
            cp_async16(so + row * ROWB + ((ch ^ (row & 7)) << 4),
                       gAp + (size_t)row * KK + kt * KCH + ch * 8);
        }
#pragma unroll
        for (int j = 0; j < 8; j++) {
            int idx = tid + j * 256;
            int row = idx >> 3, ch = idx & 7;
            cp_async16(so + ASTG + row * ROWB + ((ch ^ (row & 7)) << 4),
                       gWp + (size_t)row * KK + kt * KCH + ch * 8);
        }
    };

    load_stage(0, 0);
    asm volatile("cp.async.commit_group;\n");
    load_stage(1, 1);
    asm volatile("cp.async.commit_group;\n");

    for (int kt = 0; kt < NK; kt++) {
        if (kt < NK - 1) asm volatile("cp.async.wait_group 1;\n");
        else             asm volatile("cp.async.wait_group 0;\n");
        __syncthreads();
        // slot (kt+2)%3 was fully consumed in iteration kt-1; refill it.
        if (kt + 2 < NK) {
            load_stage(kt + 2, (kt + 2) % NSTAGE);
            asm volatile("cp.async.commit_group;\n");
        }

        const uint32_t so = sbase + (kt % NSTAGE) * STG;
#pragma unroll
        for (int ks = 0; ks < 4; ks++) {           // four k16 steps per chunk
            uint32_t a_regs[4][4];
#pragma unroll
            for (int mi = 0; mi < 4; mi++) {
                int row = wm * 64 + mi * 16 + (lane & 15);
                int ch  = ks * 2 + (lane >> 4);
                ldsm_x4(a_regs[mi], so + row * ROWB + ((ch ^ (row & 7)) << 4));
            }
            uint32_t b_regs[8][2];
#pragma unroll
            for (int p = 0; p < 4; p++) {          // each x4 covers two n-tiles
                int nrow = wn * 64 + p * 16 + ((lane >> 4) << 3) + (lane & 7);
                int ch   = ks * 2 + ((lane >> 3) & 1);
                uint32_t r[4];
                ldsm_x4(r, so + ASTG + nrow * ROWB + ((ch ^ (nrow & 7)) << 4));
                b_regs[2 * p][0] = r[0]; b_regs[2 * p][1] = r[1];
                b_regs[2 * p + 1][0] = r[2]; b_regs[2 * p + 1][1] = r[3];
            }
#pragma unroll
            for (int mi = 0; mi < 4; mi++)
#pragma unroll
                for (int ni = 0; ni < 8; ni++)
                    mma16816(acc[mi][ni], a_regs[mi], b_regs[ni]);
        }
    }

    // ---- Fused LSTM epilogue, single phase through smem ----
    float* egs = (float*)smem;                      // [128][EGS_STRIDE] = 135KB
    __syncthreads();                                // all ldsm of last chunk done
#pragma unroll
    for (int mi = 0; mi < 4; mi++)
#pragma unroll
        for (int ni = 0; ni < 8; ni++) {
            int r = wm * 64 + mi * 16 + (lane >> 2);
            int col = wn * 64 + ni * 8 + ((lane & 3) << 1);
            egs[r * EGS_STRIDE + col]           = acc[mi][ni][0];
            egs[r * EGS_STRIDE + col + 1]       = acc[mi][ni][1];
            egs[(r + 8) * EGS_STRIDE + col]     = acc[mi][ni][2];
            egs[(r + 8) * EGS_STRIDE + col + 1] = acc[mi][ni][3];
        }
    __syncthreads();
#pragma unroll 1
    for (int i = 0; i < 32; i++) {
        int item = tid + i * 256;                   // 8192 (row, hidden) items
        int ml = item >> 6, u = item & 63;
        float4 g = *(const float4*)(egs + ml * EGS_STRIDE + 4 * u);
        float4 bj = *(const float4*)(bias_s + 4 * u);
        float gi = g.x + bj.x;
        float gf = g.y + bj.y;
        float go = g.z + bj.z;
        float gc = g.w + bj.w;
        float it = 1.f / (1.f + __expf(-gi));
        float ft = 1.f / (1.f + __expf(-gf));
        float ot = 1.f / (1.f + __expf(-go));
        float tc = tanhf(gc);
        int mg = mBase + ml;
        int ug = blockIdx.x * 64 + u;
        float cv = c_in[(size_t)mg * HH + ug];
        float ct = ft * cv + it * tc;
        float ht = ot * tanhf(ct);
        out[(size_t)mg * HH + ug] = ct;
        out[(size_t)BB * HH + (size_t)mg * HH + ug] = ht;
    }
}

// ---------------------------------------------------------------------------
extern "C" void kernel_launch(void* const* d_in, const int* in_sizes, int n_in,
                              void* d_out, int out_size) {
    (void)in_sizes; (void)n_in; (void)out_size;
    const float* x  = (const float*)d_in[0];
    const float* h  = (const float*)d_in[1];
    const float* c  = (const float*)d_in[2];
    const float* Wx = (const float*)d_in[3];
    const float* bx = (const float*)d_in[4];
    const float* Wh = (const float*)d_in[5];
    const float* bh = (const float*)d_in[6];
    float* out = (float*)d_out;

    cudaFuncSetAttribute(lstm_gemm, cudaFuncAttributeMaxDynamicSharedMemorySize, SMEM_DYN);

    prep_all<<<NB_A + NB_W, 256>>>(x, h, Wx, bx, Wh, bh);
    lstm_gemm<<<dim3(NN / 256, BB / 128), 256, SMEM_DYN>>>(c, out);
}

// round 8
// speedup vs baseline: 1.5697x; 1.5697x over previous
#include <cuda_runtime.h>
#include <cuda_fp16.h>
#include <cstdint>

#define BB 32768
#define II 256
#define HH 512
#define KK 768        // I + H, single fp16 pass
#define NN 2048       // 4 * H gates

__device__ __half g_A[(size_t)BB * KK];   // [B][K]  fp16
__device__ __half g_W[(size_t)NN * KK];   // [N][K]  fp16, N interleaved (u,g)
__device__ float g_bias[NN];

// ---------------------------------------------------------------------------
// PTX helpers
// ---------------------------------------------------------------------------
__device__ __forceinline__ void cp_async16(uint32_t saddr, const void* gaddr) {
    asm volatile("cp.async.cg.shared.global [%0], [%1], 16;\n"
                 :: "r"(saddr), "l"(gaddr));
}
__device__ __forceinline__ void ldsm_x4(uint32_t* r, uint32_t addr) {
    asm volatile("ldmatrix.sync.aligned.m8n8.x4.shared.b16 {%0,%1,%2,%3}, [%4];\n"
                 : "=r"(r[0]), "=r"(r[1]), "=r"(r[2]), "=r"(r[3]) : "r"(addr));
}
__device__ __forceinline__ void mma16816(float* d, const uint32_t* a, const uint32_t* b) {
    asm volatile(
        "mma.sync.aligned.m16n8k16.row.col.f32.f16.f16.f32 "
        "{%0,%1,%2,%3}, {%4,%5,%6,%7}, {%8,%9}, {%0,%1,%2,%3};\n"
        : "+f"(d[0]), "+f"(d[1]), "+f"(d[2]), "+f"(d[3])
        : "r"(a[0]), "r"(a[1]), "r"(a[2]), "r"(a[3]), "r"(b[0]), "r"(b[1]));
}

// ---------------------------------------------------------------------------
// Merged prep kernel (fp16 A, W, bias). Gate cols interleaved:
// out col n <-> (u=n>>2, g=n&3); src row = g*H+u.
// ---------------------------------------------------------------------------
#define NB_A (BB * (KK / 4) / 256)     // 24576
#define NB_W (NN * (KK / 4) / 256)     // 1536

__global__ void prep_all(const float* __restrict__ x, const float* __restrict__ h,
                         const float* __restrict__ Wx, const float* __restrict__ bx,
                         const float* __restrict__ Wh, const float* __restrict__ bh) {
    int bidx = blockIdx.x;
    if (bidx < NB_A) {
        int idx = bidx * 256 + threadIdx.x;
        int b = idx / (KK / 4), kc = idx % (KK / 4);
        int k0 = kc * 4;
        float4 v;
        if (k0 < II) v = *(const float4*)(x + (size_t)b * II + k0);
        else         v = *(const float4*)(h + (size_t)b * HH + (k0 - II));
        union { __half h[4]; uint2 u2; } p;
        p.h[0] = __float2half_rn(v.x); p.h[1] = __float2half_rn(v.y);
        p.h[2] = __float2half_rn(v.z); p.h[3] = __float2half_rn(v.w);
        *(uint2*)(g_A + (size_t)b * KK + k0) = p.u2;
    } else {
        int idx = (bidx - NB_A) * 256 + threadIdx.x;
        int n = idx / (KK / 4), kc = idx % (KK / 4);
        int u = n >> 2, g = n & 3, src = g * HH + u;
        int k0 = kc * 4;
        float4 v;
        if (k0 < II) v = *(const float4*)(Wx + (size_t)src * II + k0);
        else         v = *(const float4*)(Wh + (size_t)src * HH + (k0 - II));
        union { __half h[4]; uint2 u2; } p;
        p.h[0] = __float2half_rn(v.x); p.h[1] = __float2half_rn(v.y);
        p.h[2] = __float2half_rn(v.z); p.h[3] = __float2half_rn(v.w);
        *(uint2*)(g_W + (size_t)n * KK + k0) = p.u2;
        if (kc == 0) g_bias[n] = bx[src] + bh[src];
    }
}

// ---------------------------------------------------------------------------
// Fused GEMM + LSTM epilogue.
// CTA tile 128x128, K chunk 64, 3-stage cp.async ring, ONE syncthreads/iter.
// 8 warps 4x2; warp tile 32x64. Rows 128B with XOR-8 swizzle (conflict-free).
// 2 CTAs/SM. Per-warp k16-step order staggered to break the post-barrier
// LSU/tensor convoy; next-stage prefetch issued after the first k16 step.
// ---------------------------------------------------------------------------
#define KCH 64
#define NK  (KK / KCH)        // 12
#define ROWB 128              // bytes per smem row (64 halves, swizzled)
#define ASTG (128 * ROWB)     // 16384 per tile
#define STG  (2 * ASTG)       // 32768 per stage (A + B)
#define NSTAGE 3
#define SMEM_DYN (NSTAGE * STG)   // 98304

__global__ void __launch_bounds__(256, 2)
lstm_gemm(const float* __restrict__ c_in, float* __restrict__ out) {
    extern __shared__ __align__(16) unsigned char smem[];
    __shared__ float bias_s[128];

    const int tid  = threadIdx.x;
    const int warp = tid >> 5, lane = tid & 31;
    const int wm = warp >> 1, wn = warp & 1;       // 4x2 warp grid
    const int mBase = blockIdx.y * 128;
    const int nBase = blockIdx.x * 128;

    const uint32_t sbase = (uint32_t)__cvta_generic_to_shared(smem);
    if (tid < 128) bias_s[tid] = g_bias[nBase + tid];

    float acc[2][8][4];
#pragma unroll
    for (int mi = 0; mi < 2; mi++)
#pragma unroll
        for (int ni = 0; ni < 8; ni++)
#pragma unroll
            for (int d = 0; d < 4; d++) acc[mi][ni][d] = 0.f;

    const __half* gAp = g_A + (size_t)mBase * KK;
    const __half* gWp = g_W + (size_t)nBase * KK;

    // A: 128 rows x 8 chunks(16B) = 1024 chunks; 4 per thread. B same.
    auto load_stage = [&](int kt, int stage) {
        uint32_t so = sbase + stage * STG;
#pragma unroll
        for (int j = 0; j < 4; j++) {
            int idx = tid + j * 256;
            int row = idx >> 3, ch = idx & 7;
            cp_async16(so + row * ROWB + ((ch ^ (row & 7)) << 4),
                       gAp + (size_t)row * KK + kt * KCH + ch * 8);
        }
#pragma unroll
        for (int j = 0; j < 4; j++) {
            int idx = tid + j * 256;
            int row = idx >> 3, ch = idx & 7;
            cp_async16(so + ASTG + row * ROWB + ((ch ^ (row & 7)) << 4),
                       gWp + (size_t)row * KK + kt * KCH + ch * 8);
        }
    };

    load_stage(0, 0);
    asm volatile("cp.async.commit_group;\n");
    load_stage(1, 1);
    asm volatile("cp.async.commit_group;\n");

    const int koff = warp & 3;     // stagger k16-step start across SMSP warps

    for (int kt = 0; kt < NK; kt++) {
        if (kt < NK - 1) asm volatile("cp.async.wait_group 1;\n");
        else             asm volatile("cp.async.wait_group 0;\n");
        __syncthreads();

        const uint32_t so = sbase + (kt % NSTAGE) * STG;
#pragma unroll
        for (int ksi = 0; ksi < 4; ksi++) {        // four k16 steps per chunk
            const int ks = (ksi + koff) & 3;       // per-warp staggered order
            uint32_t a_regs[2][4];
#pragma unroll
            for (int mi = 0; mi < 2; mi++) {
                int row = wm * 32 + mi * 16 + (lane & 15);
                int ch  = ks * 2 + (lane >> 4);
                ldsm_x4(a_regs[mi], so + row * ROWB + ((ch ^ (row & 7)) << 4));
            }
            uint32_t b_regs[8][2];
#pragma unroll
            for (int p = 0; p < 4; p++) {          // each x4 covers two n-tiles
                int nrow = wn * 64 + p * 16 + ((lane >> 4) << 3) + (lane & 7);
                int ch   = ks * 2 + ((lane >> 3) & 1);
                uint32_t r[4];
                ldsm_x4(r, so + ASTG + nrow * ROWB + ((ch ^ (nrow & 7)) << 4));
                b_regs[2 * p][0] = r[0]; b_regs[2 * p][1] = r[1];
                b_regs[2 * p + 1][0] = r[2]; b_regs[2 * p + 1][1] = r[3];
            }
#pragma unroll
            for (int mi = 0; mi < 2; mi++)
#pragma unroll
                for (int ni = 0; ni < 8; ni++)
                    mma16816(acc[mi][ni], a_regs[mi], b_regs[ni]);

            // Prefetch next+1 stage AFTER the first k16 step: keeps the
            // post-barrier window free for the ldsm storm. Slot (kt+2)%3 was
            // fully consumed in iteration kt-1 (all warps passed this iter's
            // barrier), so the refill is race-free.
            if (ksi == 0 && kt + 2 < NK) {
                load_stage(kt + 2, (kt + 2) % NSTAGE);
                asm volatile("cp.async.commit_group;\n");
            }
        }
    }

    // ---- Fused LSTM epilogue (two 64-row phases through smem) ----
    float* egs = (float*)smem;                      // [64][130] = 33280 B
#pragma unroll 1
    for (int half = 0; half < 2; half++) {
        __syncthreads();
        if ((wm >> 1) == half) {
            int rb = (wm & 1) * 32;
#pragma unroll
            for (int mi = 0; mi < 2; mi++)
#pragma unroll
                for (int ni = 0; ni < 8; ni++) {
                    int r = rb + mi * 16 + (lane >> 2);
                    int col = wn * 64 + ni * 8 + ((lane & 3) << 1);
                    egs[r * 130 + col]           = acc[mi][ni][0];
                    egs[r * 130 + col + 1]       = acc[mi][ni][1];
                    egs[(r + 8) * 130 + col]     = acc[mi][ni][2];
                    egs[(r + 8) * 130 + col + 1] = acc[mi][ni][3];
                }
        }
        __syncthreads();
#pragma unroll
        for (int i = 0; i < 8; i++) {
            int item = tid + i * 256;               // 2048 (row, hidden) items
            int ml = item >> 5, u = item & 31;
            float gi = egs[ml * 130 + 4 * u]     + bias_s[4 * u];
            float gf = egs[ml * 130 + 4 * u + 1] + bias_s[4 * u + 1];
            float go = egs[ml * 130 + 4 * u + 2] + bias_s[4 * u + 2];
            float gc = egs[ml * 130 + 4 * u + 3] + bias_s[4 * u + 3];
            float it = 1.f / (1.f + __expf(-gi));
            float ft = 1.f / (1.f + __expf(-gf));
            float ot = 1.f / (1.f + __expf(-go));
            float tc = tanhf(gc);
            int mg = mBase + half * 64 + ml;
            int ug = (nBase >> 2) + u;
            float cv = c_in[(size_t)mg * HH + ug];
            float ct = ft * cv + it * tc;
            float ht = ot * tanhf(ct);
            out[(size_t)mg * HH + ug] = ct;
            out[(size_t)BB * HH + (size_t)mg * HH + ug] = ht;
        }
    }
}

// ---------------------------------------------------------------------------
extern "C" void kernel_launch(void* const* d_in, const int* in_sizes, int n_in,
                              void* d_out, int out_size) {
    (void)in_sizes; (void)n_in; (void)out_size;
    const float* x  = (const float*)d_in[0];
    const float* h  = (const float*)d_in[1];
    const float* c  = (const float*)d_in[2];
    const float* Wx = (const float*)d_in[3];
    const float* bx = (const float*)d_in[4];
    const float* Wh = (const float*)d_in[5];
    const float* bh = (const float*)d_in[6];
    float* out = (float*)d_out;

    cudaFuncSetAttribute(lstm_gemm, cudaFuncAttributeMaxDynamicSharedMemorySize, SMEM_DYN);

    prep_all<<<NB_A + NB_W, 256>>>(x, h, Wx, bx, Wh, bh);
    lstm_gemm<<<dim3(NN / 128, BB / 128), 256, SMEM_DYN>>>(c, out);
}